// round 15
// baseline (speedup 1.0000x reference)
#include <cuda_runtime.h>
#include <cuda_bf16.h>

#define BH   128
#define LQ   4096
#define SK   4096
#define DIM  64
#define UU   45
#define NS   2            // split-S blocks per bh (16 tiles of 128 keys each)
#define NP   4            // partials per bh = NS * 2 key-halves
#define CAP  160
#define MARGIN 0.4f

// ---------------- scratch ----------------
__device__ float    g_M[BH * LQ];
__device__ int      g_topidx[BH * UU];
__device__ unsigned g_Qbf[BH * UU * 32];         // Q_reduce, bf16x2 packed, pre-scaled
__device__ float    g_Vpart[BH * NS * DIM];
__device__ float    g_actx[BH * NP * UU * DIM];
__device__ float2   g_aml[BH * NP * UU];

// ---------------- helpers ----------------
__device__ __forceinline__ unsigned packbf(float lo, float hi) {
    unsigned u; asm("cvt.rn.bf16x2.f32 %0, %1, %2;" : "=r"(u) : "f"(hi), "f"(lo)); return u;
}
__device__ __forceinline__ unsigned su32(const void* p) {
    unsigned a;
    asm("{ .reg .u64 t; cvta.to.shared.u64 t, %1; cvt.u32.u64 %0, t; }" : "=r"(a) : "l"(p));
    return a;
}
__device__ __forceinline__ void ldm4(unsigned& r0, unsigned& r1, unsigned& r2, unsigned& r3, unsigned a) {
    asm volatile("ldmatrix.sync.aligned.m8n8.x4.shared.b16 {%0,%1,%2,%3}, [%4];"
                 : "=r"(r0), "=r"(r1), "=r"(r2), "=r"(r3) : "r"(a));
}
__device__ __forceinline__ void ldm4t(unsigned& r0, unsigned& r1, unsigned& r2, unsigned& r3, unsigned a) {
    asm volatile("ldmatrix.sync.aligned.m8n8.x4.trans.shared.b16 {%0,%1,%2,%3}, [%4];"
                 : "=r"(r0), "=r"(r1), "=r"(r2), "=r"(r3) : "r"(a));
}
__device__ __forceinline__ void mma16(float* d, const unsigned* a, unsigned b0, unsigned b1) {
    asm volatile("mma.sync.aligned.m16n8k16.row.col.f32.bf16.bf16.f32 "
                 "{%0,%1,%2,%3}, {%4,%5,%6,%7}, {%8,%9}, {%0,%1,%2,%3};"
                 : "+f"(d[0]), "+f"(d[1]), "+f"(d[2]), "+f"(d[3])
                 : "r"(a[0]), "r"(a[1]), "r"(a[2]), "r"(a[3]), "r"(b0), "r"(b1));
}
__device__ __forceinline__ float qmaxf(float v) {
    v = fmaxf(v, __shfl_xor_sync(0xffffffffu, v, 1));
    v = fmaxf(v, __shfl_xor_sync(0xffffffffu, v, 2));
    return v;
}
__device__ __forceinline__ float qsumf(float v) {
    v += __shfl_xor_sync(0xffffffffu, v, 1);
    v += __shfl_xor_sync(0xffffffffu, v, 2);
    return v;
}
#define CP16(dst, src) asm volatile("cp.async.cg.shared.global [%0], [%1], 16;" :: "r"(dst), "l"(src))
#define CPCOMMIT()     asm volatile("cp.async.commit_group;" ::: "memory")
#define CPWAIT0()      asm volatile("cp.async.wait_group 0;" ::: "memory")
#define CPWAIT1()      asm volatile("cp.async.wait_group 1;" ::: "memory")

// ---------------- K1: M-tilde via single bf16 GEMM (inline K-sample gather) ----------------
__global__ __launch_bounds__(256) void k_Mb(const float* __restrict__ q,
                                            const float* __restrict__ keys,
                                            const int* __restrict__ sidx) {
    __shared__ unsigned Ksb[48 * 36];
    int bh = blockIdx.x, l0 = blockIdx.y * 128;
    int tid = threadIdx.x, w = tid >> 5, lane = tid & 31;
    int lq = lane >> 2, lr = lane & 3, mi = lane >> 3, mrow = lane & 7;

    for (int i = tid; i < 48 * 32; i += 256) {
        int u = i >> 5, c2 = i & 31;
        float2 v = make_float2(0.f, 0.f);
        if (u < UU)
            v = *(const float2*)&keys[((size_t)bh * SK + sidx[u]) * DIM + 2 * c2];
        Ksb[u * 36 + c2] = packbf(v.x, v.y);
    }

    const float* q0 = q + ((size_t)bh * LQ + l0 + 16 * w + lq) * DIM;
    const float* q1 = q0 + 8 * DIM;
    unsigned aq[4][4];
#pragma unroll
    for (int ks = 0; ks < 4; ks++) {
        float2 x0 = *(const float2*)&q0[16 * ks + 2 * lr];
        float2 x1 = *(const float2*)&q1[16 * ks + 2 * lr];
        float2 x2 = *(const float2*)&q0[16 * ks + 2 * lr + 8];
        float2 x3 = *(const float2*)&q1[16 * ks + 2 * lr + 8];
        aq[ks][0] = packbf(x0.x, x0.y);
        aq[ks][1] = packbf(x1.x, x1.y);
        aq[ks][2] = packbf(x2.x, x2.y);
        aq[ks][3] = packbf(x3.x, x3.y);
    }
    __syncthreads();

    unsigned kbase = su32(Ksb);
    float C[6][4];
#pragma unroll
    for (int n = 0; n < 6; n++) { C[n][0] = C[n][1] = C[n][2] = C[n][3] = 0.f; }
#pragma unroll
    for (int ks = 0; ks < 4; ks++) {
#pragma unroll
        for (int nt2 = 0; nt2 < 3; nt2++) {
            unsigned b0, b1, b2, b3;
            unsigned a = kbase + ((16 * nt2 + (mi & 1) * 8 + mrow) * 36 + 8 * ks + (mi >> 1) * 4) * 4;
            ldm4(b0, b1, b2, b3, a);
            mma16(C[2 * nt2],     aq[ks], b0, b2);
            mma16(C[2 * nt2 + 1], aq[ks], b1, b3);
        }
    }

    float mx0 = -1e30f, mx1 = -1e30f, sm0 = 0.f, sm1 = 0.f;
#pragma unroll
    for (int nt = 0; nt < 6; nt++) {
        int c = 8 * nt + 2 * lr;
        sm0 += C[nt][0] + C[nt][1];
        sm1 += C[nt][2] + C[nt][3];
        if (c < UU)     { mx0 = fmaxf(mx0, C[nt][0]); mx1 = fmaxf(mx1, C[nt][2]); }
        if (c + 1 < UU) { mx0 = fmaxf(mx0, C[nt][1]); mx1 = fmaxf(mx1, C[nt][3]); }
    }
    mx0 = qmaxf(mx0); mx1 = qmaxf(mx1); sm0 = qsumf(sm0); sm1 = qsumf(sm1);
    if (lr == 0) {
        g_M[bh * LQ + l0 + 16 * w + lq]     = mx0 - sm0 * (1.0f / SK);
        g_M[bh * LQ + l0 + 16 * w + lq + 8] = mx1 - sm1 * (1.0f / SK);
    }
}

// ---------------- K2: bisection threshold + exact recompute + bitonic top-45 ----------------
__global__ __launch_bounds__(256) void k_sel(const float* __restrict__ q,
                                             const float* __restrict__ keys,
                                             const int* __restrict__ sidx_g) {
    extern __shared__ float dsm[];
    float* Ks = dsm;                       // 45*64
    float* D  = Ks + UU * DIM;             // CAP*48
    __shared__ float redA[8], redB[8];
    __shared__ int   icnt[8];
    __shared__ unsigned long long skey[256];
    __shared__ int   candIdx[CAP];
    __shared__ float Mex[CAP];
    __shared__ int   sidx[UU];
    __shared__ int   cnt;
    __shared__ float bc[2];

    int bh = blockIdx.x, tid = threadIdx.x, w = tid >> 5, lane = tid & 31;

    float v[16];
#pragma unroll
    for (int j = 0; j < 16; j++) v[j] = g_M[bh * LQ + tid + 256 * j];
    if (tid == 0) cnt = 0;

    for (int i = tid; i < UU * DIM; i += 256) {
        int u = i >> 6, d = i & 63;
        Ks[i] = keys[((size_t)bh * SK + sidx_g[u]) * DIM + d];
    }

    float mn = v[0], mx = v[0];
#pragma unroll
    for (int j = 1; j < 16; j++) { mn = fminf(mn, v[j]); mx = fmaxf(mx, v[j]); }
#pragma unroll
    for (int off = 16; off; off >>= 1) {
        mn = fminf(mn, __shfl_xor_sync(0xffffffffu, mn, off));
        mx = fmaxf(mx, __shfl_xor_sync(0xffffffffu, mx, off));
    }
    if (lane == 0) { redA[w] = mn; redB[w] = mx; }
    __syncthreads();
    if (tid == 0) {
        float a = redA[0], b = redB[0];
#pragma unroll
        for (int i = 1; i < 8; i++) { a = fminf(a, redA[i]); b = fmaxf(b, redB[i]); }
        bc[0] = a; bc[1] = b;
    }
    __syncthreads();

    float lo = bc[0], hi = bc[1] + 1.0f;
    for (int it = 0; it < 14; it++) {
        float mid = 0.5f * (lo + hi);
        int c = 0;
#pragma unroll
        for (int j = 0; j < 16; j++) c += (v[j] >= mid) ? 1 : 0;
#pragma unroll
        for (int off = 16; off; off >>= 1) c += __shfl_xor_sync(0xffffffffu, c, off);
        if (lane == 0) icnt[w] = c;
        __syncthreads();
        int tot = icnt[0] + icnt[1] + icnt[2] + icnt[3] +
                  icnt[4] + icnt[5] + icnt[6] + icnt[7];
        if (tot >= UU) lo = mid; else hi = mid;
        __syncthreads();
    }
    float thr = lo - MARGIN;

#pragma unroll
    for (int j = 0; j < 16; j++) {
        if (v[j] >= thr) {
            int pos = atomicAdd(&cnt, 1);
            if (pos < CAP) candIdx[pos] = tid + 256 * j;
        }
    }
    __syncthreads();
    int ccnt = min(cnt, CAP);

    int total = ccnt * UU;
    for (int p = tid; p < total; p += 256) {
        int c = p / UU, k = p - c * UU;
        const float4* qr = (const float4*)(q + ((size_t)bh * LQ + candIdx[c]) * DIM);
        const float4* kr = (const float4*)(Ks + k * DIM);
        float acc = 0.f;
#pragma unroll
        for (int d4 = 0; d4 < 16; d4++) {
            float4 a = qr[d4], b = kr[d4];
            acc += a.x * b.x + a.y * b.y + a.z * b.z + a.w * b.w;
        }
        D[c * 48 + k] = acc;
    }
    __syncthreads();

    for (int c = tid; c < ccnt; c += 256) {
        float mxv = -1e30f, smv = 0.f;
#pragma unroll 5
        for (int k = 0; k < UU; k++) {
            float x = D[c * 48 + k];
            mxv = fmaxf(mxv, x); smv += x;
        }
        Mex[c] = mxv - smv * (1.0f / SK);
    }
    __syncthreads();

    unsigned long long key = ~0ull;
    if (tid < ccnt) {
        unsigned u = __float_as_uint(Mex[tid]);
        u = (u & 0x80000000u) ? ~u : (u | 0x80000000u);
        key = ((unsigned long long)(~u) << 32) | (unsigned)candIdx[tid];
    }
    skey[tid] = key;
    __syncthreads();
#pragma unroll
    for (int k = 2; k <= 256; k <<= 1) {
#pragma unroll
        for (int j = k >> 1; j > 0; j >>= 1) {
            int p = tid ^ j;
            if (p > tid) {
                unsigned long long a = skey[tid], b = skey[p];
                bool up = ((tid & k) == 0);
                if (up ? (a > b) : (a < b)) { skey[tid] = b; skey[p] = a; }
            }
            __syncthreads();
        }
    }
    if (tid < UU) sidx[tid] = (int)(unsigned)(skey[tid] & 0xffffffffu);
    __syncthreads();

    for (int i = tid; i < UU; i += 256) g_topidx[bh * UU + i] = sidx[i];
    for (int i = tid; i < UU * 32; i += 256) {
        int u = i >> 5, c2 = i & 31;
        float2 qv = *(const float2*)&q[((size_t)bh * LQ + sidx[u]) * DIM + 2 * c2];
        g_Qbf[(bh * UU + u) * 32 + c2] = packbf(qv.x * 0.125f, qv.y * 0.125f);
    }
}

// ---------------- K3: fused bf16 flash attention; ring-2 staging; single wave ----------------
// grid (BH, NS=2); each block: 2048 keys = 32 chunks of 64.
__global__ __launch_bounds__(256, 2) void k_attn(const float* __restrict__ K,
                                                 const float* __restrict__ V) {
    extern __shared__ unsigned dynu[];
    unsigned* Ksu = dynu;                       // 128*36
    unsigned* Vsu = dynu + 128 * 36;            // 128*36
    float*    St  = (float*)(dynu + 2 * 128 * 36);  // 2 x 8192 floats

    int bh = blockIdx.x, sp = blockIdx.y;
    int tid = threadIdx.x, w = tid >> 5, lane = tid & 31;
    int rg = w & 3, kh = w >> 2, lq = lane >> 2, lr = lane & 3;
    int mi = lane >> 3, mrow = lane & 7;

    unsigned st_s0 = su32(St), st_s1 = su32(St + 8192);
    const float* kg = K + ((size_t)bh * SK + (size_t)sp * 2048) * DIM;
    const float* vg = V + ((size_t)bh * SK + (size_t)sp * 2048) * DIM;

#define ISSUE_CHUNK(h)                                                          \
    do {                                                                        \
        unsigned sK = ((h) & 1) ? st_s1 : st_s0;                                \
        unsigned sV = sK + 4096u * 4u;                                          \
        const float* ksrc = kg + (size_t)(h) * 64 * DIM;                        \
        const float* vsrc = vg + (size_t)(h) * 64 * DIM;                        \
        _Pragma("unroll")                                                       \
        for (int c = 0; c < 4; c++) {                                           \
            CP16(sK + (unsigned)(tid + 256 * c) * 16u, ksrc + (size_t)(tid + 256 * c) * 4); \
            CP16(sV + (unsigned)(tid + 256 * c) * 16u, vsrc + (size_t)(tid + 256 * c) * 4); \
        }                                                                       \
        CPCOMMIT();                                                             \
    } while (0)

    ISSUE_CHUNK(0);
    ISSUE_CHUNK(1);

    const unsigned* qb = g_Qbf + (size_t)bh * UU * 32;
    int qr0 = 16 * rg + lq, qr1 = qr0 + 8;
    unsigned aq[4][4];
#pragma unroll
    for (int ks = 0; ks < 4; ks++) {
        aq[ks][0] = (qr0 < UU) ? qb[qr0 * 32 + 8 * ks + lr]     : 0u;
        aq[ks][1] = (qr1 < UU) ? qb[qr1 * 32 + 8 * ks + lr]     : 0u;
        aq[ks][2] = (qr0 < UU) ? qb[qr0 * 32 + 8 * ks + lr + 4] : 0u;
        aq[ks][3] = (qr1 < UU) ? qb[qr1 * 32 + 8 * ks + lr + 4] : 0u;
    }

    unsigned kbase = su32(Ksu), vbase = su32(Vsu);

    float O[8][4];
#pragma unroll
    for (int n = 0; n < 8; n++) { O[n][0] = O[n][1] = O[n][2] = O[n][3] = 0.f; }
    float m0 = -1e30f, m1 = -1e30f, l0a = 0.f, l1a = 0.f;
    float4 vacc = make_float4(0.f, 0.f, 0.f, 0.f);

    for (int h = 0; h < 32; h++) {
        if (h == 31) { CPWAIT0(); } else { CPWAIT1(); }
        __syncthreads();

        {
            const float4* stK = (const float4*)(St + ((h & 1) ? 8192 : 0));
            const float4* stV = stK + 1024;
            int rbase = 64 * (h & 1);
#pragma unroll
            for (int c = 0; c < 4; c++) {
                int i = tid + 256 * c;
                int r = rbase + (i >> 4), cb = i & 15;
                float4 f = stK[i];
                *(uint2*)&Ksu[r * 36 + 2 * cb] = make_uint2(packbf(f.x, f.y), packbf(f.z, f.w));
                float4 g = stV[i];
                vacc.x += g.x; vacc.y += g.y; vacc.z += g.z; vacc.w += g.w;
                *(uint2*)&Vsu[r * 36 + 2 * cb] = make_uint2(packbf(g.x, g.y), packbf(g.z, g.w));
            }
        }
        __syncthreads();

        if (h + 2 < 32) ISSUE_CHUNK(h + 2);

        if ((h & 1) == 0) continue;

        float C[8][4];
#pragma unroll
        for (int n = 0; n < 8; n++) { C[n][0] = C[n][1] = C[n][2] = C[n][3] = 0.f; }
#pragma unroll
        for (int ks = 0; ks < 4; ks++) {
#pragma unroll
            for (int nt2 = 0; nt2 < 4; nt2++) {
                unsigned b0, b1, b2, b3;
                unsigned a = kbase + ((64 * kh + 16 * nt2 + (mi & 1) * 8 + mrow) * 36 +
                                      8 * ks + (mi >> 1) * 4) * 4;
                ldm4(b0, b1, b2, b3, a);
                mma16(C[2 * nt2],     aq[ks], b0, b2);
                mma16(C[2 * nt2 + 1], aq[ks], b1, b3);
            }
        }

        float tm0 = -1e30f, tm1 = -1e30f;
#pragma unroll
        for (int nt = 0; nt < 8; nt++) {
            tm0 = fmaxf(tm0, fmaxf(C[nt][0], C[nt][1]));
            tm1 = fmaxf(tm1, fmaxf(C[nt][2], C[nt][3]));
        }
        tm0 = qmaxf(tm0); tm1 = qmaxf(tm1);
        float nm0 = fmaxf(m0, tm0), nm1 = fmaxf(m1, tm1);
        float f0 = __expf(m0 - nm0), f1 = __expf(m1 - nm1);
        float rs0 = 0.f, rs1 = 0.f;
#pragma unroll
        for (int nt = 0; nt < 8; nt++) {
            C[nt][0] = __expf(C[nt][0] - nm0); C[nt][1] = __expf(C[nt][1] - nm0);
            C[nt][2] = __expf(C[nt][2] - nm1); C[nt][3] = __expf(C[nt][3] - nm1);
            rs0 += C[nt][0] + C[nt][1]; rs1 += C[nt][2] + C[nt][3];
            O[nt][0] *= f0; O[nt][1] *= f0; O[nt][2] *= f1; O[nt][3] *= f1;
        }
        rs0 = qsumf(rs0); rs1 = qsumf(rs1);
        l0a = l0a * f0 + rs0; l1a = l1a * f1 + rs1;
        m0 = nm0; m1 = nm1;

#pragma unroll
        for (int ks = 0; ks < 4; ks++) {
            unsigned ap[4];
            ap[0] = packbf(C[2 * ks][0],     C[2 * ks][1]);
            ap[1] = packbf(C[2 * ks][2],     C[2 * ks][3]);
            ap[2] = packbf(C[2 * ks + 1][0], C[2 * ks + 1][1]);
            ap[3] = packbf(C[2 * ks + 1][2], C[2 * ks + 1][3]);
#pragma unroll
            for (int nd2 = 0; nd2 < 4; nd2++) {
                unsigned b0, b1, b2, b3;
                unsigned vb_a = vbase + ((64 * kh + 16 * ks + (mi & 1) * 8 + mrow) * 36 +
                                         8 * nd2 + (mi >> 1) * 4) * 4;
                ldm4t(b0, b1, b2, b3, vb_a);
                mma16(O[2 * nd2],     ap, b0, b1);
                mma16(O[2 * nd2 + 1], ap, b2, b3);
            }
        }
    }
#undef ISSUE_CHUNK

    // fp32 V colsum exchange
    float4* sm4 = (float4*)dynu;
    __syncthreads();
    sm4[tid] = vacc;
    __syncthreads();
    if (tid < 64) {
        int g = tid >> 2, j = tid & 3;
        float s = 0.f;
#pragma unroll
        for (int tt = 0; tt < 16; tt++) {
            const float* p4 = (const float*)&sm4[g + 16 * tt];
            s += p4[j];
        }
        g_Vpart[(bh * NS + sp) * DIM + tid] = s;
    }

    // store partials (p = 2*sp + kh, p in 0..3)
    int p = sp * 2 + kh;
    int r0 = 16 * rg + lq, r1 = r0 + 8;
    if (r0 < UU) {
        float* dst = &g_actx[((bh * NP + p) * UU + r0) * DIM];
#pragma unroll
        for (int nt = 0; nt < 8; nt++)
            *(float2*)&dst[8 * nt + 2 * lr] = make_float2(O[nt][0], O[nt][1]);
        if (lr == 0) g_aml[(bh * NP + p) * UU + r0] = make_float2(m0, l0a);
    }
    if (r1 < UU) {
        float* dst = &g_actx[((bh * NP + p) * UU + r1) * DIM];
#pragma unroll
        for (int nt = 0; nt < 8; nt++)
            *(float2*)&dst[8 * nt + 2 * lr] = make_float2(O[nt][2], O[nt][3]);
        if (lr == 0) g_aml[(bh * NP + p) * UU + r1] = make_float2(m1, l1a);
    }
}

// ---------------- K4: fused output (V_sum broadcast + top-row merge/scatter) ----------------
// grid (BH, 32): block covers rows [ry*128, ry*128+128).
__global__ __launch_bounds__(256) void k_out(float* __restrict__ out) {
    __shared__ float sv[64];
    __shared__ float wgt[UU * NP];
    __shared__ float Lr[UU];
    __shared__ int   idx[UU];
    int bh = blockIdx.x, ry = blockIdx.y, tid = threadIdx.x;

    if (tid < 64) {
        float s = 0.f;
#pragma unroll
        for (int sp = 0; sp < NS; sp++) s += g_Vpart[(bh * NS + sp) * DIM + tid];
        sv[tid] = s;
    }
    if (tid >= 64 && tid < 64 + UU) {
        int u = tid - 64;
        float2 ml[NP]; float mg = -1e30f;
#pragma unroll
        for (int p = 0; p < NP; p++) {
            ml[p] = g_aml[(bh * NP + p) * UU + u];
            mg = fmaxf(mg, ml[p].x);
        }
        float L = 0.f;
#pragma unroll
        for (int p = 0; p < NP; p++) {
            float wv = __expf(ml[p].x - mg);
            wgt[u * NP + p] = wv;
            L += wv * ml[p].y;
        }
        Lr[u] = L;
        idx[u] = g_topidx[bh * UU + u];
    }
    __syncthreads();

    // broadcast fill (streaming stores)
    float4* o4 = (float4*)(out + ((size_t)bh * LQ + (size_t)ry * 128) * DIM);
    float4 val = ((const float4*)sv)[tid & 15];
    for (int i = tid; i < 128 * 16; i += 256) __stcs(&o4[i], val);
    __syncthreads();

    // overwrite in-range top rows with merged context
    int lo = ry * 128, hi = lo + 128;
    for (int u = 0; u < UU; u++) {
        int l = idx[u];
        if (l >= lo && l < hi && tid < 64) {
            float s = 0.f;
#pragma unroll
            for (int p = 0; p < NP; p++)
                s += wgt[u * NP + p] * g_actx[((bh * NP + p) * UU + u) * DIM + tid];
            out[((size_t)bh * LQ + l) * DIM + tid] = s / Lr[u];
        }
    }
}

// ---------------- launch ----------------
#define ATTN_SMEM ((128 * 36 * 2) * 4 + 2 * 8192 * 4)
#define SEL_SMEM  ((UU * DIM + CAP * 48) * 4)

extern "C" void kernel_launch(void* const* d_in, const int* in_sizes, int n_in,
                              void* d_out, int out_size) {
    const float* q    = (const float*)d_in[0];
    const float* keys = (const float*)d_in[1];
    const float* vals = (const float*)d_in[2];
    const int*   sidx = (const int*)d_in[3];
    float* out = (float*)d_out;

    cudaFuncSetAttribute(k_attn, cudaFuncAttributeMaxDynamicSharedMemorySize, ATTN_SMEM);
    cudaFuncSetAttribute(k_sel,  cudaFuncAttributeMaxDynamicSharedMemorySize, SEL_SMEM);

    k_Mb<<<dim3(BH, LQ / 128), 256>>>(q, keys, sidx);
    k_sel<<<BH, 256, SEL_SMEM>>>(q, keys, sidx);
    k_attn<<<dim3(BH, NS), 256, ATTN_SMEM>>>(keys, vals);
    k_out<<<dim3(BH, LQ / 128), 256>>>(out);
}

// round 16
// speedup vs baseline: 1.0207x; 1.0207x over previous
#include <cuda_runtime.h>
#include <cuda_bf16.h>

#define BH   128
#define LQ   4096
#define SK   4096
#define DIM  64
#define UU   45
#define NS   2            // split-S blocks per bh (16 tiles of 128 keys each)
#define NP   4            // partials per bh = NS * 2 key-halves
#define CAP  160
#define MARGIN 0.4f

// ---------------- scratch ----------------
__device__ float    g_M[BH * LQ];
__device__ int      g_topidx[BH * UU];
__device__ unsigned g_Qbf[BH * UU * 32];         // Q_reduce, bf16x2 packed, pre-scaled
__device__ float    g_Vpart[BH * NS * DIM];
__device__ float    g_actx[BH * NP * UU * DIM];
__device__ float2   g_aml[BH * NP * UU];

// ---------------- helpers ----------------
__device__ __forceinline__ unsigned packbf(float lo, float hi) {
    unsigned u; asm("cvt.rn.bf16x2.f32 %0, %1, %2;" : "=r"(u) : "f"(hi), "f"(lo)); return u;
}
__device__ __forceinline__ unsigned su32(const void* p) {
    unsigned a;
    asm("{ .reg .u64 t; cvta.to.shared.u64 t, %1; cvt.u32.u64 %0, t; }" : "=r"(a) : "l"(p));
    return a;
}
__device__ __forceinline__ void ldm4(unsigned& r0, unsigned& r1, unsigned& r2, unsigned& r3, unsigned a) {
    asm volatile("ldmatrix.sync.aligned.m8n8.x4.shared.b16 {%0,%1,%2,%3}, [%4];"
                 : "=r"(r0), "=r"(r1), "=r"(r2), "=r"(r3) : "r"(a));
}
__device__ __forceinline__ void ldm4t(unsigned& r0, unsigned& r1, unsigned& r2, unsigned& r3, unsigned a) {
    asm volatile("ldmatrix.sync.aligned.m8n8.x4.trans.shared.b16 {%0,%1,%2,%3}, [%4];"
                 : "=r"(r0), "=r"(r1), "=r"(r2), "=r"(r3) : "r"(a));
}
__device__ __forceinline__ void mma16(float* d, const unsigned* a, unsigned b0, unsigned b1) {
    asm volatile("mma.sync.aligned.m16n8k16.row.col.f32.bf16.bf16.f32 "
                 "{%0,%1,%2,%3}, {%4,%5,%6,%7}, {%8,%9}, {%0,%1,%2,%3};"
                 : "+f"(d[0]), "+f"(d[1]), "+f"(d[2]), "+f"(d[3])
                 : "r"(a[0]), "r"(a[1]), "r"(a[2]), "r"(a[3]), "r"(b0), "r"(b1));
}
__device__ __forceinline__ float qmaxf(float v) {
    v = fmaxf(v, __shfl_xor_sync(0xffffffffu, v, 1));
    v = fmaxf(v, __shfl_xor_sync(0xffffffffu, v, 2));
    return v;
}
__device__ __forceinline__ float qsumf(float v) {
    v += __shfl_xor_sync(0xffffffffu, v, 1);
    v += __shfl_xor_sync(0xffffffffu, v, 2);
    return v;
}
#define CP16(dst, src) asm volatile("cp.async.cg.shared.global [%0], [%1], 16;" :: "r"(dst), "l"(src))
#define CPCOMMIT()     asm volatile("cp.async.commit_group;" ::: "memory")
#define CPWAIT0()      asm volatile("cp.async.wait_group 0;" ::: "memory")
#define CPWAIT1()      asm volatile("cp.async.wait_group 1;" ::: "memory")

// ---------------- K1: M-tilde via single bf16 GEMM (inline K-sample gather) ----------------
__global__ __launch_bounds__(256) void k_Mb(const float* __restrict__ q,
                                            const float* __restrict__ keys,
                                            const int* __restrict__ sidx) {
    __shared__ unsigned Ksb[48 * 36];
    int bh = blockIdx.x, l0 = blockIdx.y * 128;
    int tid = threadIdx.x, w = tid >> 5, lane = tid & 31;
    int lq = lane >> 2, lr = lane & 3, mi = lane >> 3, mrow = lane & 7;

    for (int i = tid; i < 48 * 32; i += 256) {
        int u = i >> 5, c2 = i & 31;
        float2 v = make_float2(0.f, 0.f);
        if (u < UU)
            v = *(const float2*)&keys[((size_t)bh * SK + sidx[u]) * DIM + 2 * c2];
        Ksb[u * 36 + c2] = packbf(v.x, v.y);
    }

    const float* q0 = q + ((size_t)bh * LQ + l0 + 16 * w + lq) * DIM;
    const float* q1 = q0 + 8 * DIM;
    unsigned aq[4][4];
#pragma unroll
    for (int ks = 0; ks < 4; ks++) {
        float2 x0 = *(const float2*)&q0[16 * ks + 2 * lr];
        float2 x1 = *(const float2*)&q1[16 * ks + 2 * lr];
        float2 x2 = *(const float2*)&q0[16 * ks + 2 * lr + 8];
        float2 x3 = *(const float2*)&q1[16 * ks + 2 * lr + 8];
        aq[ks][0] = packbf(x0.x, x0.y);
        aq[ks][1] = packbf(x1.x, x1.y);
        aq[ks][2] = packbf(x2.x, x2.y);
        aq[ks][3] = packbf(x3.x, x3.y);
    }
    __syncthreads();

    unsigned kbase = su32(Ksb);
    float C[6][4];
#pragma unroll
    for (int n = 0; n < 6; n++) { C[n][0] = C[n][1] = C[n][2] = C[n][3] = 0.f; }
#pragma unroll
    for (int ks = 0; ks < 4; ks++) {
#pragma unroll
        for (int nt2 = 0; nt2 < 3; nt2++) {
            unsigned b0, b1, b2, b3;
            unsigned a = kbase + ((16 * nt2 + (mi & 1) * 8 + mrow) * 36 + 8 * ks + (mi >> 1) * 4) * 4;
            ldm4(b0, b1, b2, b3, a);
            mma16(C[2 * nt2],     aq[ks], b0, b2);
            mma16(C[2 * nt2 + 1], aq[ks], b1, b3);
        }
    }

    float mx0 = -1e30f, mx1 = -1e30f, sm0 = 0.f, sm1 = 0.f;
#pragma unroll
    for (int nt = 0; nt < 6; nt++) {
        int c = 8 * nt + 2 * lr;
        sm0 += C[nt][0] + C[nt][1];
        sm1 += C[nt][2] + C[nt][3];
        if (c < UU)     { mx0 = fmaxf(mx0, C[nt][0]); mx1 = fmaxf(mx1, C[nt][2]); }
        if (c + 1 < UU) { mx0 = fmaxf(mx0, C[nt][1]); mx1 = fmaxf(mx1, C[nt][3]); }
    }
    mx0 = qmaxf(mx0); mx1 = qmaxf(mx1); sm0 = qsumf(sm0); sm1 = qsumf(sm1);
    if (lr == 0) {
        g_M[bh * LQ + l0 + 16 * w + lq]     = mx0 - sm0 * (1.0f / SK);
        g_M[bh * LQ + l0 + 16 * w + lq + 8] = mx1 - sm1 * (1.0f / SK);
    }
}

// ---------------- K2: bisection threshold + exact recompute + bitonic top-45 ----------------
__global__ __launch_bounds__(256) void k_sel(const float* __restrict__ q,
                                             const float* __restrict__ keys,
                                             const int* __restrict__ sidx_g) {
    extern __shared__ float dsm[];
    float* Ks = dsm;                       // 45*64
    float* D  = Ks + UU * DIM;             // CAP*48
    __shared__ float redA[8], redB[8];
    __shared__ int   icnt[8];
    __shared__ unsigned long long skey[256];
    __shared__ int   candIdx[CAP];
    __shared__ float Mex[CAP];
    __shared__ int   sidx[UU];
    __shared__ int   cnt;
    __shared__ float bc[2];

    int bh = blockIdx.x, tid = threadIdx.x, w = tid >> 5, lane = tid & 31;

    float v[16];
#pragma unroll
    for (int j = 0; j < 16; j++) v[j] = g_M[bh * LQ + tid + 256 * j];
    if (tid == 0) cnt = 0;

    for (int i = tid; i < UU * DIM; i += 256) {
        int u = i >> 6, d = i & 63;
        Ks[i] = keys[((size_t)bh * SK + sidx_g[u]) * DIM + d];
    }

    float mn = v[0], mx = v[0];
#pragma unroll
    for (int j = 1; j < 16; j++) { mn = fminf(mn, v[j]); mx = fmaxf(mx, v[j]); }
#pragma unroll
    for (int off = 16; off; off >>= 1) {
        mn = fminf(mn, __shfl_xor_sync(0xffffffffu, mn, off));
        mx = fmaxf(mx, __shfl_xor_sync(0xffffffffu, mx, off));
    }
    if (lane == 0) { redA[w] = mn; redB[w] = mx; }
    __syncthreads();
    if (tid == 0) {
        float a = redA[0], b = redB[0];
#pragma unroll
        for (int i = 1; i < 8; i++) { a = fminf(a, redA[i]); b = fmaxf(b, redB[i]); }
        bc[0] = a; bc[1] = b;
    }
    __syncthreads();

    float lo = bc[0], hi = bc[1] + 1.0f;
    for (int it = 0; it < 14; it++) {
        float mid = 0.5f * (lo + hi);
        int c = 0;
#pragma unroll
        for (int j = 0; j < 16; j++) c += (v[j] >= mid) ? 1 : 0;
#pragma unroll
        for (int off = 16; off; off >>= 1) c += __shfl_xor_sync(0xffffffffu, c, off);
        if (lane == 0) icnt[w] = c;
        __syncthreads();
        int tot = icnt[0] + icnt[1] + icnt[2] + icnt[3] +
                  icnt[4] + icnt[5] + icnt[6] + icnt[7];
        if (tot >= UU) lo = mid; else hi = mid;
        __syncthreads();
    }
    float thr = lo - MARGIN;

#pragma unroll
    for (int j = 0; j < 16; j++) {
        if (v[j] >= thr) {
            int pos = atomicAdd(&cnt, 1);
            if (pos < CAP) candIdx[pos] = tid + 256 * j;
        }
    }
    __syncthreads();
    int ccnt = min(cnt, CAP);

    int total = ccnt * UU;
    for (int p = tid; p < total; p += 256) {
        int c = p / UU, k = p - c * UU;
        const float4* qr = (const float4*)(q + ((size_t)bh * LQ + candIdx[c]) * DIM);
        const float4* kr = (const float4*)(Ks + k * DIM);
        float acc = 0.f;
#pragma unroll
        for (int d4 = 0; d4 < 16; d4++) {
            float4 a = qr[d4], b = kr[d4];
            acc += a.x * b.x + a.y * b.y + a.z * b.z + a.w * b.w;
        }
        D[c * 48 + k] = acc;
    }
    __syncthreads();

    for (int c = tid; c < ccnt; c += 256) {
        float mxv = -1e30f, smv = 0.f;
#pragma unroll 5
        for (int k = 0; k < UU; k++) {
            float x = D[c * 48 + k];
            mxv = fmaxf(mxv, x); smv += x;
        }
        Mex[c] = mxv - smv * (1.0f / SK);
    }
    __syncthreads();

    unsigned long long key = ~0ull;
    if (tid < ccnt) {
        unsigned u = __float_as_uint(Mex[tid]);
        u = (u & 0x80000000u) ? ~u : (u | 0x80000000u);
        key = ((unsigned long long)(~u) << 32) | (unsigned)candIdx[tid];
    }
    skey[tid] = key;
    __syncthreads();
#pragma unroll
    for (int k = 2; k <= 256; k <<= 1) {
#pragma unroll
        for (int j = k >> 1; j > 0; j >>= 1) {
            int p = tid ^ j;
            if (p > tid) {
                unsigned long long a = skey[tid], b = skey[p];
                bool up = ((tid & k) == 0);
                if (up ? (a > b) : (a < b)) { skey[tid] = b; skey[p] = a; }
            }
            __syncthreads();
        }
    }
    if (tid < UU) sidx[tid] = (int)(unsigned)(skey[tid] & 0xffffffffu);
    __syncthreads();

    for (int i = tid; i < UU; i += 256) g_topidx[bh * UU + i] = sidx[i];
    for (int i = tid; i < UU * 32; i += 256) {
        int u = i >> 5, c2 = i & 31;
        float2 qv = *(const float2*)&q[((size_t)bh * LQ + sidx[u]) * DIM + 2 * c2];
        g_Qbf[(bh * UU + u) * 32 + c2] = packbf(qv.x * 0.125f, qv.y * 0.125f);
    }
}

// ---------------- K3: fused bf16 flash attention; ring-2 staging; single wave ----------------
__global__ __launch_bounds__(256, 2) void k_attn(const float* __restrict__ K,
                                                 const float* __restrict__ V) {
    extern __shared__ unsigned dynu[];
    unsigned* Ksu = dynu;                       // 128*36
    unsigned* Vsu = dynu + 128 * 36;            // 128*36
    float*    St  = (float*)(dynu + 2 * 128 * 36);  // 2 x 8192 floats

    int bh = blockIdx.x, sp = blockIdx.y;
    int tid = threadIdx.x, w = tid >> 5, lane = tid & 31;
    int rg = w & 3, kh = w >> 2, lq = lane >> 2, lr = lane & 3;
    int mi = lane >> 3, mrow = lane & 7;

    unsigned st_s0 = su32(St), st_s1 = su32(St + 8192);
    const float* kg = K + ((size_t)bh * SK + (size_t)sp * 2048) * DIM;
    const float* vg = V + ((size_t)bh * SK + (size_t)sp * 2048) * DIM;

#define ISSUE_CHUNK(h)                                                          \
    do {                                                                        \
        unsigned sK = ((h) & 1) ? st_s1 : st_s0;                                \
        unsigned sV = sK + 4096u * 4u;                                          \
        const float* ksrc = kg + (size_t)(h) * 64 * DIM;                        \
        const float* vsrc = vg + (size_t)(h) * 64 * DIM;                        \
        _Pragma("unroll")                                                       \
        for (int c = 0; c < 4; c++) {                                           \
            CP16(sK + (unsigned)(tid + 256 * c) * 16u, ksrc + (size_t)(tid + 256 * c) * 4); \
            CP16(sV + (unsigned)(tid + 256 * c) * 16u, vsrc + (size_t)(tid + 256 * c) * 4); \
        }                                                                       \
        CPCOMMIT();                                                             \
    } while (0)

    ISSUE_CHUNK(0);
    ISSUE_CHUNK(1);

    const unsigned* qb = g_Qbf + (size_t)bh * UU * 32;
    int qr0 = 16 * rg + lq, qr1 = qr0 + 8;
    unsigned aq[4][4];
#pragma unroll
    for (int ks = 0; ks < 4; ks++) {
        aq[ks][0] = (qr0 < UU) ? qb[qr0 * 32 + 8 * ks + lr]     : 0u;
        aq[ks][1] = (qr1 < UU) ? qb[qr1 * 32 + 8 * ks + lr]     : 0u;
        aq[ks][2] = (qr0 < UU) ? qb[qr0 * 32 + 8 * ks + lr + 4] : 0u;
        aq[ks][3] = (qr1 < UU) ? qb[qr1 * 32 + 8 * ks + lr + 4] : 0u;
    }

    unsigned kbase = su32(Ksu), vbase = su32(Vsu);

    float O[8][4];
#pragma unroll
    for (int n = 0; n < 8; n++) { O[n][0] = O[n][1] = O[n][2] = O[n][3] = 0.f; }
    float m0 = -1e30f, m1 = -1e30f, l0a = 0.f, l1a = 0.f;
    float4 vacc = make_float4(0.f, 0.f, 0.f, 0.f);

    for (int h = 0; h < 32; h++) {
        if (h == 31) { CPWAIT0(); } else { CPWAIT1(); }
        __syncthreads();

        {
            const float4* stK = (const float4*)(St + ((h & 1) ? 8192 : 0));
            const float4* stV = stK + 1024;
            int rbase = 64 * (h & 1);
#pragma unroll
            for (int c = 0; c < 4; c++) {
                int i = tid + 256 * c;
                int r = rbase + (i >> 4), cb = i & 15;
                float4 f = stK[i];
                *(uint2*)&Ksu[r * 36 + 2 * cb] = make_uint2(packbf(f.x, f.y), packbf(f.z, f.w));
                float4 g = stV[i];
                vacc.x += g.x; vacc.y += g.y; vacc.z += g.z; vacc.w += g.w;
                *(uint2*)&Vsu[r * 36 + 2 * cb] = make_uint2(packbf(g.x, g.y), packbf(g.z, g.w));
            }
        }
        __syncthreads();

        if (h + 2 < 32) ISSUE_CHUNK(h + 2);

        if ((h & 1) == 0) continue;

        float C[8][4];
#pragma unroll
        for (int n = 0; n < 8; n++) { C[n][0] = C[n][1] = C[n][2] = C[n][3] = 0.f; }
#pragma unroll
        for (int ks = 0; ks < 4; ks++) {
#pragma unroll
            for (int nt2 = 0; nt2 < 4; nt2++) {
                unsigned b0, b1, b2, b3;
                unsigned a = kbase + ((64 * kh + 16 * nt2 + (mi & 1) * 8 + mrow) * 36 +
                                      8 * ks + (mi >> 1) * 4) * 4;
                ldm4(b0, b1, b2, b3, a);
                mma16(C[2 * nt2],     aq[ks], b0, b2);
                mma16(C[2 * nt2 + 1], aq[ks], b1, b3);
            }
        }

        float tm0 = -1e30f, tm1 = -1e30f;
#pragma unroll
        for (int nt = 0; nt < 8; nt++) {
            tm0 = fmaxf(tm0, fmaxf(C[nt][0], C[nt][1]));
            tm1 = fmaxf(tm1, fmaxf(C[nt][2], C[nt][3]));
        }
        tm0 = qmaxf(tm0); tm1 = qmaxf(tm1);
        float nm0 = fmaxf(m0, tm0), nm1 = fmaxf(m1, tm1);
        float f0 = __expf(m0 - nm0), f1 = __expf(m1 - nm1);
        float rs0 = 0.f, rs1 = 0.f;
#pragma unroll
        for (int nt = 0; nt < 8; nt++) {
            C[nt][0] = __expf(C[nt][0] - nm0); C[nt][1] = __expf(C[nt][1] - nm0);
            C[nt][2] = __expf(C[nt][2] - nm1); C[nt][3] = __expf(C[nt][3] - nm1);
            rs0 += C[nt][0] + C[nt][1]; rs1 += C[nt][2] + C[nt][3];
            O[nt][0] *= f0; O[nt][1] *= f0; O[nt][2] *= f1; O[nt][3] *= f1;
        }
        rs0 = qsumf(rs0); rs1 = qsumf(rs1);
        l0a = l0a * f0 + rs0; l1a = l1a * f1 + rs1;
        m0 = nm0; m1 = nm1;

#pragma unroll
        for (int ks = 0; ks < 4; ks++) {
            unsigned ap[4];
            ap[0] = packbf(C[2 * ks][0],     C[2 * ks][1]);
            ap[1] = packbf(C[2 * ks][2],     C[2 * ks][3]);
            ap[2] = packbf(C[2 * ks + 1][0], C[2 * ks + 1][1]);
            ap[3] = packbf(C[2 * ks + 1][2], C[2 * ks + 1][3]);
#pragma unroll
            for (int nd2 = 0; nd2 < 4; nd2++) {
                unsigned b0, b1, b2, b3;
                unsigned vb_a = vbase + ((64 * kh + 16 * ks + (mi & 1) * 8 + mrow) * 36 +
                                         8 * nd2 + (mi >> 1) * 4) * 4;
                ldm4t(b0, b1, b2, b3, vb_a);
                mma16(O[2 * nd2],     ap, b0, b1);
                mma16(O[2 * nd2 + 1], ap, b2, b3);
            }
        }
    }
#undef ISSUE_CHUNK

    // fp32 V colsum exchange
    float4* sm4 = (float4*)dynu;
    __syncthreads();
    sm4[tid] = vacc;
    __syncthreads();
    if (tid < 64) {
        int g = tid >> 2, j = tid & 3;
        float s = 0.f;
#pragma unroll
        for (int tt = 0; tt < 16; tt++) {
            const float* p4 = (const float*)&sm4[g + 16 * tt];
            s += p4[j];
        }
        g_Vpart[(bh * NS + sp) * DIM + tid] = s;
    }

    // store partials (p = 2*sp + kh, p in 0..3)
    int p = sp * 2 + kh;
    int r0 = 16 * rg + lq, r1 = r0 + 8;
    if (r0 < UU) {
        float* dst = &g_actx[((bh * NP + p) * UU + r0) * DIM];
#pragma unroll
        for (int nt = 0; nt < 8; nt++)
            *(float2*)&dst[8 * nt + 2 * lr] = make_float2(O[nt][0], O[nt][1]);
        if (lr == 0) g_aml[(bh * NP + p) * UU + r0] = make_float2(m0, l0a);
    }
    if (r1 < UU) {
        float* dst = &g_actx[((bh * NP + p) * UU + r1) * DIM];
#pragma unroll
        for (int nt = 0; nt < 8; nt++)
            *(float2*)&dst[8 * nt + 2 * lr] = make_float2(O[nt][2], O[nt][3]);
        if (lr == 0) g_aml[(bh * NP + p) * UU + r1] = make_float2(m1, l1a);
    }
}

// ---------------- K4: broadcast V_sum into entire output (streaming stores) ----------------
__global__ void k_fill(float* __restrict__ out) {
    __shared__ float sv[64];
    int bh = blockIdx.x, ry = blockIdx.y, tid = threadIdx.x;
    if (tid < 64) {
        float s = 0.f;
#pragma unroll
        for (int sp = 0; sp < NS; sp++) s += g_Vpart[(bh * NS + sp) * DIM + tid];
        sv[tid] = s;
    }
    __syncthreads();
    float4* o4 = (float4*)(out + ((size_t)bh * LQ + (size_t)ry * 128) * DIM);
    float4 val = ((const float4*)sv)[tid & 15];
    for (int i = tid; i < 128 * 16; i += 256) __stcs(&o4[i], val);
}

// ---------------- K5: merge 4 partials, normalize, scatter (one block per bh) ----------------
__global__ void k_combine(float* __restrict__ out) {
    __shared__ float wgt[UU * NP];
    __shared__ float Lr[UU];
    __shared__ int   idx[UU];
    int bh = blockIdx.x, tid = threadIdx.x;
    if (tid < UU) {
        float2 ml[NP]; float mg = -1e30f;
#pragma unroll
        for (int p = 0; p < NP; p++) {
            ml[p] = g_aml[(bh * NP + p) * UU + tid];
            mg = fmaxf(mg, ml[p].x);
        }
        float L = 0.f;
#pragma unroll
        for (int p = 0; p < NP; p++) {
            float wv = __expf(ml[p].x - mg);
            wgt[tid * NP + p] = wv;
            L += wv * ml[p].y;
        }
        Lr[tid] = L;
        idx[tid] = g_topidx[bh * UU + tid];
    }
    __syncthreads();
    for (int i = tid; i < UU * DIM; i += 256) {
        int u = i >> 6, d = i & 63;
        float s = 0.f;
#pragma unroll
        for (int p = 0; p < NP; p++)
            s += wgt[u * NP + p] * g_actx[((bh * NP + p) * UU + u) * DIM + d];
        out[((size_t)bh * LQ + idx[u]) * DIM + d] = s / Lr[u];
    }
}

// ---------------- launch ----------------
#define ATTN_SMEM ((128 * 36 * 2) * 4 + 2 * 8192 * 4)
#define SEL_SMEM  ((UU * DIM + CAP * 48) * 4)

extern "C" void kernel_launch(void* const* d_in, const int* in_sizes, int n_in,
                              void* d_out, int out_size) {
    const float* q    = (const float*)d_in[0];
    const float* keys = (const float*)d_in[1];
    const float* vals = (const float*)d_in[2];
    const int*   sidx = (const int*)d_in[3];
    float* out = (float*)d_out;

    cudaFuncSetAttribute(k_attn, cudaFuncAttributeMaxDynamicSharedMemorySize, ATTN_SMEM);
    cudaFuncSetAttribute(k_sel,  cudaFuncAttributeMaxDynamicSharedMemorySize, SEL_SMEM);

    k_Mb<<<dim3(BH, LQ / 128), 256>>>(q, keys, sidx);
    k_sel<<<BH, 256, SEL_SMEM>>>(q, keys, sidx);
    k_attn<<<dim3(BH, NS), 256, ATTN_SMEM>>>(keys, vals);
    k_fill<<<dim3(BH, LQ / 128), 256>>>(out);
    k_combine<<<BH, 256>>>(out);
}

// round 17
// speedup vs baseline: 1.0244x; 1.0036x over previous
#include <cuda_runtime.h>
#include <cuda_bf16.h>

#define BH   128
#define LQ   4096
#define SK   4096
#define DIM  64
#define UU   45
#define NS   2            // split-S blocks per bh (16 tiles of 128 keys each)
#define NP   4            // partials per bh = NS * 2 key-halves
#define CAP  160
#define MARGIN 0.4f

// ---------------- scratch ----------------
__device__ float    g_M[BH * LQ];
__device__ int      g_topidx[BH * UU];
__device__ unsigned g_Qbf[BH * UU * 32];         // Q_reduce, bf16x2 packed, pre-scaled
__device__ float    g_Vpart[BH * NS * DIM];
__device__ float    g_actx[BH * NP * UU * DIM];
__device__ float2   g_aml[BH * NP * UU];

// ---------------- helpers ----------------
__device__ __forceinline__ unsigned packbf(float lo, float hi) {
    unsigned u; asm("cvt.rn.bf16x2.f32 %0, %1, %2;" : "=r"(u) : "f"(hi), "f"(lo)); return u;
}
__device__ __forceinline__ unsigned su32(const void* p) {
    unsigned a;
    asm("{ .reg .u64 t; cvta.to.shared.u64 t, %1; cvt.u32.u64 %0, t; }" : "=r"(a) : "l"(p));
    return a;
}
__device__ __forceinline__ void ldm4(unsigned& r0, unsigned& r1, unsigned& r2, unsigned& r3, unsigned a) {
    asm volatile("ldmatrix.sync.aligned.m8n8.x4.shared.b16 {%0,%1,%2,%3}, [%4];"
                 : "=r"(r0), "=r"(r1), "=r"(r2), "=r"(r3) : "r"(a));
}
__device__ __forceinline__ void ldm4t(unsigned& r0, unsigned& r1, unsigned& r2, unsigned& r3, unsigned a) {
    asm volatile("ldmatrix.sync.aligned.m8n8.x4.trans.shared.b16 {%0,%1,%2,%3}, [%4];"
                 : "=r"(r0), "=r"(r1), "=r"(r2), "=r"(r3) : "r"(a));
}
__device__ __forceinline__ void mma16(float* d, const unsigned* a, unsigned b0, unsigned b1) {
    asm volatile("mma.sync.aligned.m16n8k16.row.col.f32.bf16.bf16.f32 "
                 "{%0,%1,%2,%3}, {%4,%5,%6,%7}, {%8,%9}, {%0,%1,%2,%3};"
                 : "+f"(d[0]), "+f"(d[1]), "+f"(d[2]), "+f"(d[3])
                 : "r"(a[0]), "r"(a[1]), "r"(a[2]), "r"(a[3]), "r"(b0), "r"(b1));
}
__device__ __forceinline__ float qmaxf(float v) {
    v = fmaxf(v, __shfl_xor_sync(0xffffffffu, v, 1));
    v = fmaxf(v, __shfl_xor_sync(0xffffffffu, v, 2));
    return v;
}
__device__ __forceinline__ float qsumf(float v) {
    v += __shfl_xor_sync(0xffffffffu, v, 1);
    v += __shfl_xor_sync(0xffffffffu, v, 2);
    return v;
}
#define CP16(dst, src) asm volatile("cp.async.cg.shared.global [%0], [%1], 16;" :: "r"(dst), "l"(src))
#define CPCOMMIT()     asm volatile("cp.async.commit_group;" ::: "memory")
#define CPWAIT0()      asm volatile("cp.async.wait_group 0;" ::: "memory")
#define CPWAIT1()      asm volatile("cp.async.wait_group 1;" ::: "memory")

// ---------------- K1: M-tilde via single bf16 GEMM (inline K-sample gather) ----------------
__global__ __launch_bounds__(256) void k_Mb(const float* __restrict__ q,
                                            const float* __restrict__ keys,
                                            const int* __restrict__ sidx) {
    __shared__ unsigned Ksb[48 * 36];
    int bh = blockIdx.x, l0 = blockIdx.y * 128;
    int tid = threadIdx.x, w = tid >> 5, lane = tid & 31;
    int lq = lane >> 2, lr = lane & 3, mi = lane >> 3, mrow = lane & 7;

    for (int i = tid; i < 48 * 32; i += 256) {
        int u = i >> 5, c2 = i & 31;
        float2 v = make_float2(0.f, 0.f);
        if (u < UU)
            v = *(const float2*)&keys[((size_t)bh * SK + sidx[u]) * DIM + 2 * c2];
        Ksb[u * 36 + c2] = packbf(v.x, v.y);
    }

    const float* q0 = q + ((size_t)bh * LQ + l0 + 16 * w + lq) * DIM;
    const float* q1 = q0 + 8 * DIM;
    unsigned aq[4][4];
#pragma unroll
    for (int ks = 0; ks < 4; ks++) {
        float2 x0 = *(const float2*)&q0[16 * ks + 2 * lr];
        float2 x1 = *(const float2*)&q1[16 * ks + 2 * lr];
        float2 x2 = *(const float2*)&q0[16 * ks + 2 * lr + 8];
        float2 x3 = *(const float2*)&q1[16 * ks + 2 * lr + 8];
        aq[ks][0] = packbf(x0.x, x0.y);
        aq[ks][1] = packbf(x1.x, x1.y);
        aq[ks][2] = packbf(x2.x, x2.y);
        aq[ks][3] = packbf(x3.x, x3.y);
    }
    __syncthreads();

    unsigned kbase = su32(Ksb);
    float C[6][4];
#pragma unroll
    for (int n = 0; n < 6; n++) { C[n][0] = C[n][1] = C[n][2] = C[n][3] = 0.f; }
#pragma unroll
    for (int ks = 0; ks < 4; ks++) {
#pragma unroll
        for (int nt2 = 0; nt2 < 3; nt2++) {
            unsigned b0, b1, b2, b3;
            unsigned a = kbase + ((16 * nt2 + (mi & 1) * 8 + mrow) * 36 + 8 * ks + (mi >> 1) * 4) * 4;
            ldm4(b0, b1, b2, b3, a);
            mma16(C[2 * nt2],     aq[ks], b0, b2);
            mma16(C[2 * nt2 + 1], aq[ks], b1, b3);
        }
    }

    float mx0 = -1e30f, mx1 = -1e30f, sm0 = 0.f, sm1 = 0.f;
#pragma unroll
    for (int nt = 0; nt < 6; nt++) {
        int c = 8 * nt + 2 * lr;
        sm0 += C[nt][0] + C[nt][1];
        sm1 += C[nt][2] + C[nt][3];
        if (c < UU)     { mx0 = fmaxf(mx0, C[nt][0]); mx1 = fmaxf(mx1, C[nt][2]); }
        if (c + 1 < UU) { mx0 = fmaxf(mx0, C[nt][1]); mx1 = fmaxf(mx1, C[nt][3]); }
    }
    mx0 = qmaxf(mx0); mx1 = qmaxf(mx1); sm0 = qsumf(sm0); sm1 = qsumf(sm1);
    if (lr == 0) {
        g_M[bh * LQ + l0 + 16 * w + lq]     = mx0 - sm0 * (1.0f / SK);
        g_M[bh * LQ + l0 + 16 * w + lq + 8] = mx1 - sm1 * (1.0f / SK);
    }
}

// ---------------- K2: bisection threshold + exact recompute + bitonic top-45 ----------------
__global__ __launch_bounds__(256) void k_sel(const float* __restrict__ q,
                                             const float* __restrict__ keys,
                                             const int* __restrict__ sidx_g) {
    extern __shared__ float dsm[];
    float* Ks = dsm;                       // 45*64
    float* D  = Ks + UU * DIM;             // CAP*48
    __shared__ float redA[8], redB[8];
    __shared__ int   icnt[8];
    __shared__ unsigned long long skey[256];
    __shared__ int   candIdx[CAP];
    __shared__ float Mex[CAP];
    __shared__ int   sidx[UU];
    __shared__ int   cnt;
    __shared__ float bc[2];

    int bh = blockIdx.x, tid = threadIdx.x, w = tid >> 5, lane = tid & 31;

    float v[16];
#pragma unroll
    for (int j = 0; j < 16; j++) v[j] = g_M[bh * LQ + tid + 256 * j];
    if (tid == 0) cnt = 0;

    for (int i = tid; i < UU * DIM; i += 256) {
        int u = i >> 6, d = i & 63;
        Ks[i] = keys[((size_t)bh * SK + sidx_g[u]) * DIM + d];
    }

    float mn = v[0], mx = v[0];
#pragma unroll
    for (int j = 1; j < 16; j++) { mn = fminf(mn, v[j]); mx = fmaxf(mx, v[j]); }
#pragma unroll
    for (int off = 16; off; off >>= 1) {
        mn = fminf(mn, __shfl_xor_sync(0xffffffffu, mn, off));
        mx = fmaxf(mx, __shfl_xor_sync(0xffffffffu, mx, off));
    }
    if (lane == 0) { redA[w] = mn; redB[w] = mx; }
    __syncthreads();
    if (tid == 0) {
        float a = redA[0], b = redB[0];
#pragma unroll
        for (int i = 1; i < 8; i++) { a = fminf(a, redA[i]); b = fmaxf(b, redB[i]); }
        bc[0] = a; bc[1] = b;
    }
    __syncthreads();

    float lo = bc[0], hi = bc[1] + 1.0f;
    for (int it = 0; it < 14; it++) {
        float mid = 0.5f * (lo + hi);
        int c = 0;
#pragma unroll
        for (int j = 0; j < 16; j++) c += (v[j] >= mid) ? 1 : 0;
#pragma unroll
        for (int off = 16; off; off >>= 1) c += __shfl_xor_sync(0xffffffffu, c, off);
        if (lane == 0) icnt[w] = c;
        __syncthreads();
        int tot = icnt[0] + icnt[1] + icnt[2] + icnt[3] +
                  icnt[4] + icnt[5] + icnt[6] + icnt[7];
        if (tot >= UU) lo = mid; else hi = mid;
        __syncthreads();
    }
    float thr = lo - MARGIN;

#pragma unroll
    for (int j = 0; j < 16; j++) {
        if (v[j] >= thr) {
            int pos = atomicAdd(&cnt, 1);
            if (pos < CAP) candIdx[pos] = tid + 256 * j;
        }
    }
    __syncthreads();
    int ccnt = min(cnt, CAP);

    int total = ccnt * UU;
    for (int p = tid; p < total; p += 256) {
        int c = p / UU, k = p - c * UU;
        const float4* qr = (const float4*)(q + ((size_t)bh * LQ + candIdx[c]) * DIM);
        const float4* kr = (const float4*)(Ks + k * DIM);
        float acc = 0.f;
#pragma unroll
        for (int d4 = 0; d4 < 16; d4++) {
            float4 a = qr[d4], b = kr[d4];
            acc += a.x * b.x + a.y * b.y + a.z * b.z + a.w * b.w;
        }
        D[c * 48 + k] = acc;
    }
    __syncthreads();

    for (int c = tid; c < ccnt; c += 256) {
        float mxv = -1e30f, smv = 0.f;
#pragma unroll 5
        for (int k = 0; k < UU; k++) {
            float x = D[c * 48 + k];
            mxv = fmaxf(mxv, x); smv += x;
        }
        Mex[c] = mxv - smv * (1.0f / SK);
    }
    __syncthreads();

    unsigned long long key = ~0ull;
    if (tid < ccnt) {
        unsigned u = __float_as_uint(Mex[tid]);
        u = (u & 0x80000000u) ? ~u : (u | 0x80000000u);
        key = ((unsigned long long)(~u) << 32) | (unsigned)candIdx[tid];
    }
    skey[tid] = key;
    __syncthreads();
#pragma unroll
    for (int k = 2; k <= 256; k <<= 1) {
#pragma unroll
        for (int j = k >> 1; j > 0; j >>= 1) {
            int p = tid ^ j;
            if (p > tid) {
                unsigned long long a = skey[tid], b = skey[p];
                bool up = ((tid & k) == 0);
                if (up ? (a > b) : (a < b)) { skey[tid] = b; skey[p] = a; }
            }
            __syncthreads();
        }
    }
    if (tid < UU) sidx[tid] = (int)(unsigned)(skey[tid] & 0xffffffffu);
    __syncthreads();

    for (int i = tid; i < UU; i += 256) g_topidx[bh * UU + i] = sidx[i];
    for (int i = tid; i < UU * 32; i += 256) {
        int u = i >> 5, c2 = i & 31;
        float2 qv = *(const float2*)&q[((size_t)bh * LQ + sidx[u]) * DIM + 2 * c2];
        g_Qbf[(bh * UU + u) * 32 + c2] = packbf(qv.x * 0.125f, qv.y * 0.125f);
    }
}

// ---------------- K3: fused bf16 flash attention; ring-2 staging; single wave ----------------
__global__ __launch_bounds__(256, 2) void k_attn(const float* __restrict__ K,
                                                 const float* __restrict__ V) {
    extern __shared__ unsigned dynu[];
    unsigned* Ksu = dynu;                       // 128*36
    unsigned* Vsu = dynu + 128 * 36;            // 128*36
    float*    St  = (float*)(dynu + 2 * 128 * 36);  // 2 x 8192 floats

    int bh = blockIdx.x, sp = blockIdx.y;
    int tid = threadIdx.x, w = tid >> 5, lane = tid & 31;
    int rg = w & 3, kh = w >> 2, lq = lane >> 2, lr = lane & 3;
    int mi = lane >> 3, mrow = lane & 7;

    unsigned st_s0 = su32(St), st_s1 = su32(St + 8192);
    const float* kg = K + ((size_t)bh * SK + (size_t)sp * 2048) * DIM;
    const float* vg = V + ((size_t)bh * SK + (size_t)sp * 2048) * DIM;

#define ISSUE_CHUNK(h)                                                          \
    do {                                                                        \
        unsigned sK = ((h) & 1) ? st_s1 : st_s0;                                \
        unsigned sV = sK + 4096u * 4u;                                          \
        const float* ksrc = kg + (size_t)(h) * 64 * DIM;                        \
        const float* vsrc = vg + (size_t)(h) * 64 * DIM;                        \
        _Pragma("unroll")                                                       \
        for (int c = 0; c < 4; c++) {                                           \
            CP16(sK + (unsigned)(tid + 256 * c) * 16u, ksrc + (size_t)(tid + 256 * c) * 4); \
            CP16(sV + (unsigned)(tid + 256 * c) * 16u, vsrc + (size_t)(tid + 256 * c) * 4); \
        }                                                                       \
        CPCOMMIT();                                                             \
    } while (0)

    ISSUE_CHUNK(0);
    ISSUE_CHUNK(1);

    const unsigned* qb = g_Qbf + (size_t)bh * UU * 32;
    int qr0 = 16 * rg + lq, qr1 = qr0 + 8;
    unsigned aq[4][4];
#pragma unroll
    for (int ks = 0; ks < 4; ks++) {
        aq[ks][0] = (qr0 < UU) ? qb[qr0 * 32 + 8 * ks + lr]     : 0u;
        aq[ks][1] = (qr1 < UU) ? qb[qr1 * 32 + 8 * ks + lr]     : 0u;
        aq[ks][2] = (qr0 < UU) ? qb[qr0 * 32 + 8 * ks + lr + 4] : 0u;
        aq[ks][3] = (qr1 < UU) ? qb[qr1 * 32 + 8 * ks + lr + 4] : 0u;
    }

    unsigned kbase = su32(Ksu), vbase = su32(Vsu);

    float O[8][4];
#pragma unroll
    for (int n = 0; n < 8; n++) { O[n][0] = O[n][1] = O[n][2] = O[n][3] = 0.f; }
    float m0 = -1e30f, m1 = -1e30f, l0a = 0.f, l1a = 0.f;
    float4 vacc = make_float4(0.f, 0.f, 0.f, 0.f);

    for (int h = 0; h < 32; h++) {
        if (h == 31) { CPWAIT0(); } else { CPWAIT1(); }
        __syncthreads();

        {
            const float4* stK = (const float4*)(St + ((h & 1) ? 8192 : 0));
            const float4* stV = stK + 1024;
            int rbase = 64 * (h & 1);
#pragma unroll
            for (int c = 0; c < 4; c++) {
                int i = tid + 256 * c;
                int r = rbase + (i >> 4), cb = i & 15;
                float4 f = stK[i];
                *(uint2*)&Ksu[r * 36 + 2 * cb] = make_uint2(packbf(f.x, f.y), packbf(f.z, f.w));
                float4 g = stV[i];
                vacc.x += g.x; vacc.y += g.y; vacc.z += g.z; vacc.w += g.w;
                *(uint2*)&Vsu[r * 36 + 2 * cb] = make_uint2(packbf(g.x, g.y), packbf(g.z, g.w));
            }
        }
        __syncthreads();

        if (h + 2 < 32) ISSUE_CHUNK(h + 2);

        if ((h & 1) == 0) continue;

        float C[8][4];
#pragma unroll
        for (int n = 0; n < 8; n++) { C[n][0] = C[n][1] = C[n][2] = C[n][3] = 0.f; }
#pragma unroll
        for (int ks = 0; ks < 4; ks++) {
#pragma unroll
            for (int nt2 = 0; nt2 < 4; nt2++) {
                unsigned b0, b1, b2, b3;
                unsigned a = kbase + ((64 * kh + 16 * nt2 + (mi & 1) * 8 + mrow) * 36 +
                                      8 * ks + (mi >> 1) * 4) * 4;
                ldm4(b0, b1, b2, b3, a);
                mma16(C[2 * nt2],     aq[ks], b0, b2);
                mma16(C[2 * nt2 + 1], aq[ks], b1, b3);
            }
        }

        float tm0 = -1e30f, tm1 = -1e30f;
#pragma unroll
        for (int nt = 0; nt < 8; nt++) {
            tm0 = fmaxf(tm0, fmaxf(C[nt][0], C[nt][1]));
            tm1 = fmaxf(tm1, fmaxf(C[nt][2], C[nt][3]));
        }
        tm0 = qmaxf(tm0); tm1 = qmaxf(tm1);
        float nm0 = fmaxf(m0, tm0), nm1 = fmaxf(m1, tm1);
        float f0 = __expf(m0 - nm0), f1 = __expf(m1 - nm1);
        float rs0 = 0.f, rs1 = 0.f;
#pragma unroll
        for (int nt = 0; nt < 8; nt++) {
            C[nt][0] = __expf(C[nt][0] - nm0); C[nt][1] = __expf(C[nt][1] - nm0);
            C[nt][2] = __expf(C[nt][2] - nm1); C[nt][3] = __expf(C[nt][3] - nm1);
            rs0 += C[nt][0] + C[nt][1]; rs1 += C[nt][2] + C[nt][3];
            O[nt][0] *= f0; O[nt][1] *= f0; O[nt][2] *= f1; O[nt][3] *= f1;
        }
        rs0 = qsumf(rs0); rs1 = qsumf(rs1);
        l0a = l0a * f0 + rs0; l1a = l1a * f1 + rs1;
        m0 = nm0; m1 = nm1;

#pragma unroll
        for (int ks = 0; ks < 4; ks++) {
            unsigned ap[4];
            ap[0] = packbf(C[2 * ks][0],     C[2 * ks][1]);
            ap[1] = packbf(C[2 * ks][2],     C[2 * ks][3]);
            ap[2] = packbf(C[2 * ks + 1][0], C[2 * ks + 1][1]);
            ap[3] = packbf(C[2 * ks + 1][2], C[2 * ks + 1][3]);
#pragma unroll
            for (int nd2 = 0; nd2 < 4; nd2++) {
                unsigned b0, b1, b2, b3;
                unsigned vb_a = vbase + ((64 * kh + 16 * ks + (mi & 1) * 8 + mrow) * 36 +
                                         8 * nd2 + (mi >> 1) * 4) * 4;
                ldm4t(b0, b1, b2, b3, vb_a);
                mma16(O[2 * nd2],     ap, b0, b1);
                mma16(O[2 * nd2 + 1], ap, b2, b3);
            }
        }
    }
#undef ISSUE_CHUNK

    // fp32 V colsum exchange
    float4* sm4 = (float4*)dynu;
    __syncthreads();
    sm4[tid] = vacc;
    __syncthreads();
    if (tid < 64) {
        int g = tid >> 2, j = tid & 3;
        float s = 0.f;
#pragma unroll
        for (int tt = 0; tt < 16; tt++) {
            const float* p4 = (const float*)&sm4[g + 16 * tt];
            s += p4[j];
        }
        g_Vpart[(bh * NS + sp) * DIM + tid] = s;
    }

    // store partials (p = 2*sp + kh, p in 0..3)
    int p = sp * 2 + kh;
    int r0 = 16 * rg + lq, r1 = r0 + 8;
    if (r0 < UU) {
        float* dst = &g_actx[((bh * NP + p) * UU + r0) * DIM];
#pragma unroll
        for (int nt = 0; nt < 8; nt++)
            *(float2*)&dst[8 * nt + 2 * lr] = make_float2(O[nt][0], O[nt][1]);
        if (lr == 0) g_aml[(bh * NP + p) * UU + r0] = make_float2(m0, l0a);
    }
    if (r1 < UU) {
        float* dst = &g_actx[((bh * NP + p) * UU + r1) * DIM];
#pragma unroll
        for (int nt = 0; nt < 8; nt++)
            *(float2*)&dst[8 * nt + 2 * lr] = make_float2(O[nt][2], O[nt][3]);
        if (lr == 0) g_aml[(bh * NP + p) * UU + r1] = make_float2(m1, l1a);
    }
}

// ---------------- K4: broadcast V_sum into entire output (streaming stores) ----------------
__global__ void k_fill(float* __restrict__ out) {
    __shared__ float sv[64];
    int bh = blockIdx.x, ry = blockIdx.y, tid = threadIdx.x;
    if (tid < 64) {
        float s = 0.f;
#pragma unroll
        for (int sp = 0; sp < NS; sp++) s += g_Vpart[(bh * NS + sp) * DIM + tid];
        sv[tid] = s;
    }
    __syncthreads();
    float4* o4 = (float4*)(out + ((size_t)bh * LQ + (size_t)ry * 128) * DIM);
    float4 val = ((const float4*)sv)[tid & 15];
    for (int i = tid; i < 128 * 16; i += 256) __stcs(&o4[i], val);
}

// ---------------- K5: merge 4 partials, normalize, scatter (one block per bh) ----------------
__global__ void k_combine(float* __restrict__ out) {
    __shared__ float wgt[UU * NP];
    __shared__ float Lr[UU];
    __shared__ int   idx[UU];
    int bh = blockIdx.x, tid = threadIdx.x;
    if (tid < UU) {
        float2 ml[NP]; float mg = -1e30f;
#pragma unroll
        for (int p = 0; p < NP; p++) {
            ml[p] = g_aml[(bh * NP + p) * UU + tid];
            mg = fmaxf(mg, ml[p].x);
        }
        float L = 0.f;
#pragma unroll
        for (int p = 0; p < NP; p++) {
            float wv = __expf(ml[p].x - mg);
            wgt[tid * NP + p] = wv;
            L += wv * ml[p].y;
        }
        Lr[tid] = L;
        idx[tid] = g_topidx[bh * UU + tid];
    }
    __syncthreads();
    for (int i = tid; i < UU * DIM; i += 256) {
        int u = i >> 6, d = i & 63;
        float s = 0.f;
#pragma unroll
        for (int p = 0; p < NP; p++)
            s += wgt[u * NP + p] * g_actx[((bh * NP + p) * UU + u) * DIM + d];
        out[((size_t)bh * LQ + idx[u]) * DIM + d] = s / Lr[u];
    }
}

// ---------------- launch ----------------
#define ATTN_SMEM ((128 * 36 * 2) * 4 + 2 * 8192 * 4)
#define SEL_SMEM  ((UU * DIM + CAP * 48) * 4)

extern "C" void kernel_launch(void* const* d_in, const int* in_sizes, int n_in,
                              void* d_out, int out_size) {
    const float* q    = (const float*)d_in[0];
    const float* keys = (const float*)d_in[1];
    const float* vals = (const float*)d_in[2];
    const int*   sidx = (const int*)d_in[3];
    float* out = (float*)d_out;

    cudaFuncSetAttribute(k_attn, cudaFuncAttributeMaxDynamicSharedMemorySize, ATTN_SMEM);
    cudaFuncSetAttribute(k_sel,  cudaFuncAttributeMaxDynamicSharedMemorySize, SEL_SMEM);

    k_Mb<<<dim3(BH, LQ / 128), 256>>>(q, keys, sidx);
    k_sel<<<BH, 256, SEL_SMEM>>>(q, keys, sidx);
    k_attn<<<dim3(BH, NS), 256, ATTN_SMEM>>>(keys, vals);
    k_fill<<<dim3(BH, LQ / 128), 256>>>(out);
    k_combine<<<BH, 256>>>(out);
}